// round 17
// baseline (speedup 1.0000x reference)
#include <cuda_runtime.h>
#include <cuda_fp16.h>
#include <math.h>
#include <stdint.h>

#define BATCH 2
#define SEQ   2048
#define DM    1024
#define NH    16
#define HD    64
#define MTOT  (BATCH*SEQ)   // 4096

// ---------------- scratch (allocation-free) ----------------
__device__ __half g_aq[MTOT * DM];
__device__ __half g_ak[MTOT * DM];
__device__ __half g_av[MTOT * DM];
__device__ __half g_wt0[DM * DM];
__device__ __half g_wt1[DM * DM];
__device__ __half g_wt2[DM * DM];
__device__ __half g_wto[DM * DM];
__device__ __half g_qh[MTOT * DM];
__device__ __half g_kh[MTOT * DM];
__device__ __half g_vh[MTOT * DM];
__device__ __half g_ao[MTOT * DM];

// fp16 mma m16n8k16, fp32 accum
__device__ __forceinline__ void mma_f16(float d[4],
    uint32_t a0, uint32_t a1, uint32_t a2, uint32_t a3,
    uint32_t b0, uint32_t b1) {
    asm volatile(
        "mma.sync.aligned.m16n8k16.row.col.f32.f16.f16.f32 "
        "{%0,%1,%2,%3}, {%4,%5,%6,%7}, {%8,%9}, {%0,%1,%2,%3};\n"
        : "+f"(d[0]), "+f"(d[1]), "+f"(d[2]), "+f"(d[3])
        : "r"(a0), "r"(a1), "r"(a2), "r"(a3), "r"(b0), "r"(b1));
}

__device__ __forceinline__ void ldm_x4(uint32_t& r0, uint32_t& r1,
                                       uint32_t& r2, uint32_t& r3, uint32_t addr) {
    asm volatile("ldmatrix.sync.aligned.m8n8.x4.shared.b16 {%0,%1,%2,%3}, [%4];"
        : "=r"(r0), "=r"(r1), "=r"(r2), "=r"(r3) : "r"(addr));
}
__device__ __forceinline__ void ldm_x4_t(uint32_t& r0, uint32_t& r1,
                                         uint32_t& r2, uint32_t& r3, uint32_t addr) {
    asm volatile("ldmatrix.sync.aligned.m8n8.x4.trans.shared.b16 {%0,%1,%2,%3}, [%4];"
        : "=r"(r0), "=r"(r1), "=r"(r2), "=r"(r3) : "r"(addr));
}
__device__ __forceinline__ uint32_t sm_u32(const void* p) {
    return (uint32_t)__cvta_generic_to_shared(p);
}
__device__ __forceinline__ void cpa16(uint32_t dst, const void* src) {
    asm volatile("cp.async.cg.shared.global [%0], [%1], 16;" :: "r"(dst), "l"(src));
}
#define CP_COMMIT() asm volatile("cp.async.commit_group;" ::: "memory")
#define CP_WAIT1()  asm volatile("cp.async.wait_group 1;" ::: "memory")

// ---------------- prep kernels ----------------
__global__ __launch_bounds__(256)
void conv3(const float* __restrict__ q, const float* __restrict__ k,
           const float* __restrict__ v, __half* __restrict__ oq,
           __half* __restrict__ ok, __half* __restrict__ ov, int n8) {
    int i = blockIdx.x * 256 + threadIdx.x;
    if (i >= n8) return;
    const float* in = (blockIdx.y == 0) ? q : (blockIdx.y == 1) ? k : v;
    __half* out = (blockIdx.y == 0) ? oq : (blockIdx.y == 1) ? ok : ov;
    float4 v0 = ((const float4*)in)[2 * i];
    float4 v1 = ((const float4*)in)[2 * i + 1];
    __half2 p0 = __floats2half2_rn(v0.x, v0.y);
    __half2 p1 = __floats2half2_rn(v0.z, v0.w);
    __half2 p2 = __floats2half2_rn(v1.x, v1.y);
    __half2 p3 = __floats2half2_rn(v1.z, v1.w);
    uint4 o;
    o.x = *(uint32_t*)&p0; o.y = *(uint32_t*)&p1;
    o.z = *(uint32_t*)&p2; o.w = *(uint32_t*)&p3;
    ((uint4*)out)[i] = o;
}

// W[K][N] fp32 -> Wt[N][K] fp16 (scaled)
__device__ __forceinline__ void transpose_body(const float* __restrict__ W,
                                               __half* __restrict__ Wt, float scale) {
    __shared__ float tile[32][33];
    const int k0 = blockIdx.x * 32, n0 = blockIdx.y * 32;
    const int tx = threadIdx.x, ty = threadIdx.y;   // 32 x 8
    #pragma unroll
    for (int r = 0; r < 4; r++)
        tile[ty + 8 * r][tx] = W[(size_t)(k0 + ty + 8 * r) * DM + n0 + tx];
    __syncthreads();
    #pragma unroll
    for (int r = 0; r < 4; r++)
        Wt[(size_t)(n0 + ty + 8 * r) * DM + k0 + tx] =
            __float2half_rn(tile[tx][ty + 8 * r] * scale);
}

__global__ __launch_bounds__(256)
void trans3(const float* __restrict__ W0, const float* __restrict__ W1,
            const float* __restrict__ W2, __half* __restrict__ T0,
            __half* __restrict__ T1, __half* __restrict__ T2, float qs) {
    const int z = blockIdx.z;
    const float* W = (z == 0) ? W0 : (z == 1) ? W1 : W2;
    __half* T = (z == 0) ? T0 : (z == 1) ? T1 : T2;
    transpose_body(W, T, (z == 0) ? qs : 1.f);
}

__global__ __launch_bounds__(256)
void trans1(const float* __restrict__ W, __half* __restrict__ T) {
    transpose_body(W, T, 1.f);
}

// ---------------- fp16 GEMM (cp.async 3-stage, BK=32, 32 chunks) ----------------
// CTA 128x128, 8 warps (4x2), warp 32x64. Row stride 20 u32 = 80 B.
// smem 61,440 B -> 3 CTAs/SM (the occupancy lever).
#define GSTR 20
#define NCHUNK 32                           // DM / 32
#define TILE_U32 (128 * GSTR)               // one 128x32 fp16 tile = 2560 u32
#define STAGE_BYTES (2 * TILE_U32 * 4)      // A+B = 20480
#define GEMM_SMEM (3 * STAGE_BYTES)         // 61440

__device__ __forceinline__ void gemm_body(const __half* __restrict__ A,
        const __half* __restrict__ Wt, const float* __restrict__ bias, float bscale,
        float* __restrict__ Cf, __half* __restrict__ Ch) {
    extern __shared__ uint32_t gsm[];
    const int tid = threadIdx.x;
    const int wid = tid >> 5, lane = tid & 31, g = lane >> 2, t = lane & 3;
    const int lrow = lane & 15, lhi = lane >> 4;
    const int n0 = blockIdx.x * 128, m0 = blockIdx.y * 128;
    const int wm = (wid >> 1) * 32, wn = (wid & 1) * 64;

    const uint32_t smBase = sm_u32(gsm);

    auto issue = [&](int c, int s) {
        const uint32_t aB = smBase + s * STAGE_BYTES;
        const uint32_t bB = aB + TILE_U32 * 4;
        #pragma unroll
        for (int it = 0; it < 2; it++) {
            int idx = tid + it * 256;            // 0..511
            int row = idx >> 2, col = idx & 3;   // 128 rows x 4 x 16B
            uint32_t off = (uint32_t)((row * GSTR + col * 4) * 4);
            cpa16(aB + off, &A[(size_t)(m0 + row) * DM + c * 32 + col * 8]);
            cpa16(bB + off, &Wt[(size_t)(n0 + row) * DM + c * 32 + col * 8]);
        }
        CP_COMMIT();
    };

    issue(0, 0);
    issue(1, 1);

    float acc[16][4] = {};
    const uint32_t aOff = (uint32_t)(((wm + lrow) * GSTR + lhi * 4) * 4);
    const uint32_t bOff = (uint32_t)(TILE_U32 * 4 + ((wn + lrow) * GSTR + lhi * 4) * 4);

    #pragma unroll 1
    for (int c = 0; c < NCHUNK; c++) {
        const int st = c - (c / 3) * 3;
        CP_WAIT1();
        __syncthreads();
        if (c + 2 < NCHUNK) {
            int cn = c + 2;
            issue(cn, cn - (cn / 3) * 3);
        } else {
            CP_COMMIT();   // empty group keeps wait_group 1 sound at the tail
        }
        const uint32_t aB = smBase + st * STAGE_BYTES + aOff;
        const uint32_t bB = smBase + st * STAGE_BYTES + bOff;
        #pragma unroll
        for (int kk = 0; kk < 2; kk++) {
            uint32_t af[2][4], bf[8][2];
            #pragma unroll
            for (int mt = 0; mt < 2; mt++)
                ldm_x4(af[mt][0], af[mt][1], af[mt][2], af[mt][3],
                       aB + (uint32_t)(mt * 16 * GSTR * 4 + kk * 32));
            #pragma unroll
            for (int np = 0; np < 4; np++) {
                uint32_t r0, r1, r2, r3;
                ldm_x4(r0, r1, r2, r3, bB + (uint32_t)(np * 16 * GSTR * 4 + kk * 32));
                bf[2 * np][0] = r0; bf[2 * np + 1][0] = r1;
                bf[2 * np][1] = r2; bf[2 * np + 1][1] = r3;
            }
            #pragma unroll
            for (int mt = 0; mt < 2; mt++)
                #pragma unroll
                for (int nt = 0; nt < 8; nt++)
                    mma_f16(acc[mt * 8 + nt], af[mt][0], af[mt][1], af[mt][2], af[mt][3],
                            bf[nt][0], bf[nt][1]);
        }
    }

    #pragma unroll
    for (int mt = 0; mt < 2; mt++) {
        int row = m0 + wm + mt * 16 + g;
        #pragma unroll
        for (int nt = 0; nt < 8; nt++) {
            int col = n0 + wn + nt * 8 + 2 * t;
            float b0 = bias[col] * bscale, b1 = bias[col + 1] * bscale;
            float* a = acc[mt * 8 + nt];
            float v00 = a[0] + b0, v01 = a[1] + b1;
            float v10 = a[2] + b0, v11 = a[3] + b1;
            if (Cf) {
                float2 x0 = { v00, v01 };
                *(float2*)&Cf[(size_t)row * DM + col] = x0;
                float2 x1 = { v10, v11 };
                *(float2*)&Cf[(size_t)(row + 8) * DM + col] = x1;
            }
            if (Ch) {
                __half2 h0 = __floats2half2_rn(v00, v01);
                *(uint32_t*)&Ch[(size_t)row * DM + col] = *(uint32_t*)&h0;
                __half2 h1 = __floats2half2_rn(v10, v11);
                *(uint32_t*)&Ch[(size_t)(row + 8) * DM + col] = *(uint32_t*)&h1;
            }
        }
    }
}

__global__ __launch_bounds__(256, 3)
void gemm3(const __half* __restrict__ aq, const __half* __restrict__ ak,
           const __half* __restrict__ av, const __half* __restrict__ w0,
           const __half* __restrict__ w1, const __half* __restrict__ w2,
           const float* __restrict__ bq, const float* __restrict__ bk,
           const float* __restrict__ bv, __half* __restrict__ oq,
           __half* __restrict__ ok, __half* __restrict__ ov, float qscale) {
    const int z = blockIdx.z;
    const __half* A  = (z == 0) ? aq : (z == 1) ? ak : av;
    const __half* Wt = (z == 0) ? w0 : (z == 1) ? w1 : w2;
    const float* bias = (z == 0) ? bq : (z == 1) ? bk : bv;
    __half* Ch = (z == 0) ? oq : (z == 1) ? ok : ov;
    gemm_body(A, Wt, bias, (z == 0) ? qscale : 1.f, nullptr, Ch);
}

__global__ __launch_bounds__(256, 3)
void gemm1(const __half* __restrict__ A, const __half* __restrict__ Wt,
           const float* __restrict__ bias, float* __restrict__ Cf) {
    gemm_body(A, Wt, bias, 1.f, Cf, nullptr);
}

// ---------------- fp16 flash attention ----------------
// causal, cp.async 3-stage K/V, ldmatrix(+trans for V), h2exp2 softmax.
// CTA = 128 queries of one (b,h); 8 warps, warp = 16 queries x 64 keys.
// Descending-qb launch order: heaviest CTAs first (causal tail fix).
#define AQ 36
#define ASTG (2 * 64 * AQ)                       // u32 per stage (K+V) = 4608
#define ASTB (ASTG * 4)                          // 18432 B
#define ATTN_SMEM_BYTES ((128 * AQ + 3 * ASTG) * 4)   // 73728

__global__ __launch_bounds__(256, 2)
void attn_h(const __half* __restrict__ qh, const __half* __restrict__ kh,
            const __half* __restrict__ vh, __half* __restrict__ out) {
    extern __shared__ uint32_t smA[];
    uint32_t* Qs = smA;                          // [128][AQ]

    const int tid = threadIdx.x;
    const int w = tid >> 5, lane = tid & 31, g = lane >> 2, t = lane & 3;
    const int lrow = lane & 15, lhi = lane >> 4;
    const int qb = (int)gridDim.x - 1 - (int)blockIdx.x;   // big qb launches first
    const int h = blockIdx.y, bb = blockIdx.z;
    const int q0 = qb * 128, wq = w * 16;

    const __half* Qb = qh + (size_t)bb * SEQ * DM + h * HD;
    const __half* Kb = kh + (size_t)bb * SEQ * DM + h * HD;
    const __half* Vb = vh + (size_t)bb * SEQ * DM + h * HD;

    const uint32_t smBase = sm_u32(smA);
    const uint32_t stage0 = smBase + 128 * AQ * 4;

    const int ntiles = 2 * qb + 2;

    auto issue = [&](int jt, int s) {
        const uint32_t kB = stage0 + s * ASTB;
        const uint32_t vB = kB + 64 * AQ * 4;
        const int j0 = jt * 64;
        #pragma unroll
        for (int it = 0; it < 2; it++) {
            int idx = tid + it * 256;            // 0..511
            int row = idx >> 3, col = idx & 7;
            uint32_t off = (uint32_t)((row * AQ + col * 4) * 4);
            cpa16(kB + off, &Kb[(size_t)(j0 + row) * DM + col * 8]);
            cpa16(vB + off, &Vb[(size_t)(j0 + row) * DM + col * 8]);
        }
        CP_COMMIT();
    };

    #pragma unroll
    for (int r = 0; r < 4; r++) {
        int idx = tid + r * 256, row = idx >> 3, c = idx & 7;
        uint4 v = *(const uint4*)&Qb[(size_t)(q0 + row) * DM + c * 8];
        *(uint4*)&Qs[row * AQ + c * 4] = v;
    }

    issue(0, 0);
    issue(1, 1);

    const uint32_t qBase = smBase + (uint32_t)(((wq + lrow) * AQ + lhi * 4) * 4);
    const uint32_t kFrag = stage0 + (uint32_t)((lrow * AQ + lhi * 4) * 4);
    const uint32_t vFrag = stage0 + (uint32_t)(64 * AQ * 4 + lrow * AQ * 4 + lhi * 16);

    float ofr[8][4] = {};
    float m0 = -1e30f, m1 = -1e30f, l0 = 0.f, l1 = 0.f;

    #pragma unroll 1
    for (int jt = 0; jt < ntiles; jt++) {
        const int j0 = jt * 64;
        const int st = jt - (jt / 3) * 3;
        CP_WAIT1();
        __syncthreads();
        if (jt + 2 < ntiles) {
            int jn = jt + 2;
            issue(jn, jn - (jn / 3) * 3);
        } else {
            CP_COMMIT();
        }

        const uint32_t kStage = kFrag + st * ASTB;
        const uint32_t vStage = vFrag + st * ASTB;

        // S = Q K^T
        float sc[8][4] = {};
        #pragma unroll
        for (int kk = 0; kk < 4; kk++) {
            uint32_t a0, a1, a2, a3;
            ldm_x4(a0, a1, a2, a3, qBase + (uint32_t)(kk * 32));
            #pragma unroll
            for (int np = 0; np < 4; np++) {
                uint32_t r0, r1, r2, r3;
                ldm_x4(r0, r1, r2, r3,
                       kStage + (uint32_t)(np * 16 * AQ * 4 + kk * 32));
                mma_f16(sc[2 * np],     a0, a1, a2, a3, r0, r2);
                mma_f16(sc[2 * np + 1], a0, a1, a2, a3, r1, r3);
            }
        }

        // causal mask
        if (j0 + 63 > q0 + wq) {
            int r0 = q0 + wq + g, r1 = r0 + 8;
            #pragma unroll
            for (int nt = 0; nt < 8; nt++) {
                int key = j0 + nt * 8 + 2 * t;
                if (key > r0)     sc[nt][0] = -1e30f;
                if (key + 1 > r0) sc[nt][1] = -1e30f;
                if (key > r1)     sc[nt][2] = -1e30f;
                if (key + 1 > r1) sc[nt][3] = -1e30f;
            }
        }

        // online softmax (base-2; scale folded into Wq/bq)
        float tm0 = -1e30f, tm1 = -1e30f;
        #pragma unroll
        for (int nt = 0; nt < 8; nt++) {
            tm0 = fmaxf(tm0, fmaxf(sc[nt][0], sc[nt][1]));
            tm1 = fmaxf(tm1, fmaxf(sc[nt][2], sc[nt][3]));
        }
        tm0 = fmaxf(tm0, __shfl_xor_sync(0xffffffffu, tm0, 1));
        tm0 = fmaxf(tm0, __shfl_xor_sync(0xffffffffu, tm0, 2));
        tm1 = fmaxf(tm1, __shfl_xor_sync(0xffffffffu, tm1, 1));
        tm1 = fmaxf(tm1, __shfl_xor_sync(0xffffffffu, tm1, 2));

        float nm0 = fmaxf(m0, tm0), nm1 = fmaxf(m1, tm1);
        float al0 = exp2f(m0 - nm0), al1 = exp2f(m1 - nm1);
        m0 = nm0; m1 = nm1;

        // P = 2^(S - m) in packed fp16; half2 IS the PV A-fragment.
        uint32_t pl[8], ph_[8];
        float rs0 = 0.f, rs1 = 0.f;
        #pragma unroll
        for (int nt = 0; nt < 8; nt++) {
            __half2 x0 = __floats2half2_rn(sc[nt][0] - nm0, sc[nt][1] - nm0);
            __half2 p0 = h2exp2(x0);
            pl[nt] = *(uint32_t*)&p0;
            float2 f0 = __half22float2(p0);
            rs0 += f0.x + f0.y;
            __half2 x1 = __floats2half2_rn(sc[nt][2] - nm1, sc[nt][3] - nm1);
            __half2 p1 = h2exp2(x1);
            ph_[nt] = *(uint32_t*)&p1;
            float2 f1 = __half22float2(p1);
            rs1 += f1.x + f1.y;
        }
        rs0 += __shfl_xor_sync(0xffffffffu, rs0, 1);
        rs0 += __shfl_xor_sync(0xffffffffu, rs0, 2);
        rs1 += __shfl_xor_sync(0xffffffffu, rs1, 1);
        rs1 += __shfl_xor_sync(0xffffffffu, rs1, 2);
        l0 = l0 * al0 + rs0;
        l1 = l1 * al1 + rs1;

        #pragma unroll
        for (int nt = 0; nt < 8; nt++) {
            ofr[nt][0] *= al0; ofr[nt][1] *= al0;
            ofr[nt][2] *= al1; ofr[nt][3] *= al1;
        }

        // O += P @ V  (V raw [key][d]; ldmatrix.trans gives V^T B-frags)
        #pragma unroll
        for (int c = 0; c < 4; c++) {
            uint32_t pa0 = pl[2 * c], pa1 = ph_[2 * c];
            uint32_t pa2 = pl[2 * c + 1], pa3 = ph_[2 * c + 1];
            #pragma unroll
            for (int dp = 0; dp < 4; dp++) {
                uint32_t r0, r1, r2, r3;
                ldm_x4_t(r0, r1, r2, r3,
                         vStage + (uint32_t)(c * 16 * AQ * 4 + dp * 32));
                mma_f16(ofr[2 * dp],     pa0, pa1, pa2, pa3, r0, r1);
                mma_f16(ofr[2 * dp + 1], pa0, pa1, pa2, pa3, r2, r3);
            }
        }
    }

    const float inv0 = 1.f / l0, inv1 = 1.f / l1;
    const int row0 = q0 + wq + g;
    #pragma unroll
    for (int dt = 0; dt < 8; dt++) {
        int col = h * HD + dt * 8 + 2 * t;
        __half2 v0 = __floats2half2_rn(ofr[dt][0] * inv0, ofr[dt][1] * inv0);
        *(uint32_t*)&out[((size_t)bb * SEQ + row0) * DM + col] = *(uint32_t*)&v0;
        __half2 v1 = __floats2half2_rn(ofr[dt][2] * inv1, ofr[dt][3] * inv1);
        *(uint32_t*)&out[((size_t)bb * SEQ + row0 + 8) * DM + col] = *(uint32_t*)&v1;
    }
}

// ----------------------------------------------------------------------------
extern "C" void kernel_launch(void* const* d_in, const int* in_sizes, int n_in,
                              void* d_out, int out_size) {
    const float* q  = (const float*)d_in[0];
    const float* k  = (const float*)d_in[1];
    const float* v  = (const float*)d_in[2];
    const float* Wq = (const float*)d_in[3];
    const float* bq = (const float*)d_in[4];
    const float* Wk = (const float*)d_in[5];
    const float* bk = (const float*)d_in[6];
    const float* Wv = (const float*)d_in[7];
    const float* bv = (const float*)d_in[8];
    const float* Wo = (const float*)d_in[9];
    const float* bo = (const float*)d_in[10];
    float* out = (float*)d_out;

    __half *aq, *ak, *av, *w0, *w1, *w2, *wo, *qh, *kh, *vh, *ao;
    cudaGetSymbolAddress((void**)&aq, g_aq);
    cudaGetSymbolAddress((void**)&ak, g_ak);
    cudaGetSymbolAddress((void**)&av, g_av);
    cudaGetSymbolAddress((void**)&w0, g_wt0);
    cudaGetSymbolAddress((void**)&w1, g_wt1);
    cudaGetSymbolAddress((void**)&w2, g_wt2);
    cudaGetSymbolAddress((void**)&wo, g_wto);
    cudaGetSymbolAddress((void**)&qh, g_qh);
    cudaGetSymbolAddress((void**)&kh, g_kh);
    cudaGetSymbolAddress((void**)&vh, g_vh);
    cudaGetSymbolAddress((void**)&ao, g_ao);

    const float QSCALE = 0.125f * 1.44269504088896f;  // 1/sqrt(64) * log2(e)
    const int n8 = MTOT * DM / 8;

    cudaFuncSetAttribute(attn_h, cudaFuncAttributeMaxDynamicSharedMemorySize,
                         ATTN_SMEM_BYTES);
    cudaFuncSetAttribute(gemm3, cudaFuncAttributeMaxDynamicSharedMemorySize,
                         GEMM_SMEM);
    cudaFuncSetAttribute(gemm1, cudaFuncAttributeMaxDynamicSharedMemorySize,
                         GEMM_SMEM);

    conv3<<<dim3(n8 / 256, 3), 256>>>(q, k, v, aq, ak, av, n8);
    trans3<<<dim3(DM / 32, DM / 32, 3), dim3(32, 8)>>>(Wq, Wk, Wv, w0, w1, w2, QSCALE);
    trans1<<<dim3(DM / 32, DM / 32), dim3(32, 8)>>>(Wo, wo);
    gemm3<<<dim3(DM / 128, MTOT / 128, 3), 256, GEMM_SMEM>>>(aq, ak, av, w0, w1, w2,
                                                  bq, bk, bv, qh, kh, vh, QSCALE);
    attn_h<<<dim3(SEQ / 128, NH, BATCH), 256, ATTN_SMEM_BYTES>>>(qh, kh, vh, ao);

    gemm1<<<dim3(DM / 128, MTOT / 128), 256, GEMM_SMEM>>>(ao, wo, bo, out);
}